// round 15
// baseline (speedup 1.0000x reference)
#include <cuda_runtime.h>
#include <cuda_fp16.h>
#include <cstdint>

// ---------------- problem constants ----------------
#define F_    32
#define B_    6
#define C_    1024
#define HF    14
#define NB    27
#define T_    5
#define OUTP  3
#define SPAT  9
#define NBOX  (F_*B_)           // 192
#define K1    (C_*SPAT)         // 9216
#define N1    (3*512)           // 1536
#define M1    (NBOX*SPAT)       // 1728
#define M1P   1792              // 14*128, pad rows stay zero (.bss)
#define K2    (512*27)          // 13824
#define M2    (NBOX*3)          // 576 = 9*64
#define N2    256
#define SPLIT1 4
#define KIT1  72                // 9216/4/32
#define SPLIT2 16
#define KIT2  27                // 13824/16/32

// ---------------- scratch ----------------
__device__ int   g_map[NBOX*T_];
__device__ __align__(16) __half g_A0[(size_t)M1P*K1];  // im2col fp16 (pad zero)
__device__ __align__(16) __half g_B1[(size_t)N1*K1];   // w1a [n][k] fp16
__device__ float g_P [(size_t)SPLIT1*M1*N1];           // G1 split-K partials
__device__ __align__(16) __half g_yh[(size_t)NBOX*5*4608];
__device__ __align__(16) __half g_B2[(size_t)N2*K2];   // w1b [n][k] fp16
__device__ float g_C2p[(size_t)SPLIT2*M2*N2];

// ---------------- helpers ----------------
__device__ __forceinline__ void cpasync16(uint32_t dst, const void* src) {
    asm volatile("cp.async.cg.shared.global [%0], [%1], 16;"
                 :: "r"(dst), "l"(__cvta_generic_to_global(src)) : "memory");
}
__device__ __forceinline__ uint32_t smem_u32(const void* p) {
    uint32_t a;
    asm("{ .reg .u64 t; cvta.to.shared.u64 t, %1; cvt.u32.u64 %0, t; }"
        : "=r"(a) : "l"(p));
    return a;
}
#define CP_COMMIT() asm volatile("cp.async.commit_group;" ::: "memory")
#define CP_WAIT2()  asm volatile("cp.async.wait_group 2;" ::: "memory")
#define LDSM4(rr, a) asm volatile( \
    "ldmatrix.sync.aligned.m8n8.x4.shared.b16 {%0,%1,%2,%3}, [%4];" \
    : "=r"((rr)[0]),"=r"((rr)[1]),"=r"((rr)[2]),"=r"((rr)[3]) : "r"(a))
__device__ __forceinline__ void mma_f16(float* d, const uint32_t* a,
                                        uint32_t b0, uint32_t b1) {
    asm volatile(
        "mma.sync.aligned.m16n8k16.row.col.f32.f16.f16.f32 "
        "{%0,%1,%2,%3}, {%4,%5,%6,%7}, {%8,%9}, {%0,%1,%2,%3};"
        : "+f"(d[0]), "+f"(d[1]), "+f"(d[2]), "+f"(d[3])
        : "r"(a[0]), "r"(a[1]), "r"(a[2]), "r"(a[3]), "r"(b0), "r"(b1));
}
// conflict-free swizzle (see R13): bank-quads of rows 0..7 = {0,4,1,5,2,6,3,7}
__device__ __forceinline__ uint32_t swz(int row, int ckl) {
    return (uint32_t)row*64u + (uint32_t)((ckl ^ ((row >> 1) & 3)) << 4);
}
__device__ __forceinline__ uint32_t pack2(__half a, __half b) {
    __half2 h2 = __halves2half2(a, b);
    return *(uint32_t*)&h2;
}

// ---------------- fused prep: roi+im2col | w1a | w1b | map ----------------
__global__ void __launch_bounds__(256)
prep_all(const float* __restrict__ fmaps, const float* __restrict__ boxes,
         const int* __restrict__ person_ids,
         const float* __restrict__ w1a, const float* __restrict__ w1b) {
    extern __shared__ char dyn[];
    const int bb = blockIdx.x;
    const int tid = threadIdx.x;

    if (bb < 192) {
        // ---------- ROI align + im2col ----------
        __half* sroi = (__half*)dyn;             // 9216 halves = 18KB
        __shared__ int   sy0[6], sy1[6], sx0[6], sx1[6];
        __shared__ float sly[6], slx[6];
        int nb = bb;
        int f  = nb / B_;
        if (tid < 12) {
            int  j   = tid % 6;
            bool isx = tid >= 6;
            float x1 = boxes[nb*4+0], y1 = boxes[nb*4+1];
            float x2 = boxes[nb*4+2], y2 = boxes[nb*4+3];
            float bw = fmaxf(x2 - x1, 1.0f) / (float)OUTP;
            float bh = fmaxf(y2 - y1, 1.0f) / (float)OUTP;
            float gj = (float)(j >> 1) + ((float)(j & 1) + 0.5f) * 0.5f;
            if (isx) {
                float xs  = x1 + bw * gj;
                float x0f = fminf(fmaxf(floorf(xs), 0.f), (float)(HF-1));
                float lx  = fminf(fmaxf(xs - x0f, 0.f), 1.f);
                int x0 = (int)x0f;
                sx0[j] = x0; sx1[j] = min(x0+1, HF-1); slx[j] = lx;
            } else {
                float ys  = y1 + bh * gj;
                float y0f = fminf(fmaxf(floorf(ys), 0.f), (float)(HF-1));
                float ly  = fminf(fmaxf(ys - y0f, 0.f), 1.f);
                int y0 = (int)y0f;
                sy0[j] = y0; sy1[j] = min(y0+1, HF-1); sly[j] = ly;
            }
        }
        __syncthreads();
        const float* base = fmaps + (size_t)f * C_ * HF * HF;
        for (int idx = tid; idx < C_*SPAT; idx += 256) {
            int c = idx / SPAT, o = idx % SPAT;
            int oi = o / 3, oj = o % 3;
            const float* fm = base + (size_t)c * HF * HF;
            float acc = 0.f;
            #pragma unroll
            for (int s = 0; s < 4; s++) {
                int jy = oi*2 + (s >> 1);
                int jx = oj*2 + (s & 1);
                float ly = sly[jy], lx = slx[jx];
                int y0 = sy0[jy], y1i = sy1[jy], x0 = sx0[jx], x1i = sx1[jx];
                acc += fm[y0*HF + x0]  * (1.f-ly)*(1.f-lx)
                     + fm[y0*HF + x1i] * (1.f-ly)*lx
                     + fm[y1i*HF + x0] * ly*(1.f-lx)
                     + fm[y1i*HF + x1i]* ly*lx;
            }
            sroi[idx] = __float2half(acc * 0.25f);
        }
        __syncthreads();
        const __half hz = __float2half(0.f);
        #pragma unroll
        for (int sp = 0; sp < SPAT; sp++) {
            int h = sp / 3, w = sp % 3;
            uint32_t* dst = (uint32_t*)(g_A0 + ((size_t)(nb*9 + sp)) * K1);
            for (int jj = tid; jj < K1/2; jj += 256) {
                int j0 = 2*jj, j1 = 2*jj + 1;
                int ci0 = j0 / 9, t0 = j0 % 9;
                int ci1 = j1 / 9, t1 = j1 % 9;
                int h0 = h + t0/3 - 1, w0 = w + t0%3 - 1;
                int h1 = h + t1/3 - 1, w1 = w + t1%3 - 1;
                __half v0 = (h0 >= 0 && h0 < 3 && w0 >= 0 && w0 < 3)
                            ? sroi[ci0*9 + h0*3 + w0] : hz;
                __half v1 = (h1 >= 0 && h1 < 3 && w1 >= 0 && w1 < 3)
                            ? sroi[ci1*9 + h1*3 + w1] : hz;
                dst[jj] = pack2(v0, v1);
            }
        }
    } else if (bb < 704) {
        // ---------- w1a: linear smem fp16, gather on read ----------
        __half* sh = (__half*)dyn;               // 27648 halves = 55296B
        int co = bb - 192;
        const float* src = w1a + (size_t)co * 27648;
        for (int i = tid; i < 27648; i += 256)
            sh[i] = __float2half(src[i]);        // conflict-free STS
        __syncthreads();
        #pragma unroll
        for (int kd = 0; kd < 3; kd++) {
            uint32_t* dst = (uint32_t*)(g_B1 + ((size_t)(kd*512 + co)) * 9216);
            const int kb = kd * 9;
            for (int jj = tid; jj < 4608; jj += 256) {
                int j0 = 2*jj, j1 = j0 + 1;
                int ci0 = j0 / 9, t0 = j0 % 9;
                int ci1 = j1 / 9, t1 = j1 % 9;
                dst[jj] = pack2(sh[ci0*27 + kb + t0], sh[ci1*27 + kb + t1]);
            }
        }
    } else if (bb < 960) {
        // ---------- w1b: linear smem fp16, gather on read ----------
        __half* sh = (__half*)dyn;               // 13824 halves = 27648B
        int n = bb - 704;
        const float* src = w1b + (size_t)n * 13824;
        for (int i = tid; i < 13824; i += 256)
            sh[i] = __float2half(src[i]);
        __syncthreads();
        uint32_t* dst = (uint32_t*)(g_B2 + (size_t)n * 13824);
        for (int jj = tid; jj < 6912; jj += 256) {
            int j = 2*jj;
            int q = j >> 9, ci = j & 511;        // pairs never cross q
            dst[jj] = pack2(sh[ci*27 + q], sh[(ci+1)*27 + q]);
        }
    } else {
        // ---------- temporal index + person matching ----------
        int n = tid;
        if (n < NBOX) {
            int f = n / B_, b = n % B_;
            int pid = person_ids[f*B_ + b];
            int start = max(f - T_/2, 0);
            int end   = min(start + T_ - 1, F_ - 1);
            for (int t = 0; t < T_; t++) {
                int g = (int)((float)start + (float)(t*(end-start)) / (float)(T_-1));
                int m = -1;
                for (int bp = 0; bp < B_; bp++)
                    if (person_ids[g*B_ + bp] == pid) m = g*B_ + bp;
                g_map[n*T_ + t] = m;
            }
        }
    }
}

// ---------------- G1 GEMM: CTA 128x128, warp 32x64, fixed swizzle ----------
// 4-stage cp.async (16KB/stage = A 8KB + B 8KB), one barrier/iter, occ 2.
__global__ void __launch_bounds__(256, 2)
gemm_g1(const __half* __restrict__ A0, const __half* __restrict__ B0,
        float* __restrict__ C) {
    extern __shared__ char smem[];
    const uint32_t sb = smem_u32(smem);
    const int tid = threadIdx.x;
    const int lane = tid & 31, wid = tid >> 5;
    const int warp_m = wid & 3, warp_n = wid >> 2;
    const int g = lane >> 2, t4 = lane & 3;
    const int row0 = blockIdx.y * 128;
    const int col0 = blockIdx.x * 128;
    const int kStart = blockIdx.z * KIT1 * 32;

    // load geometry: 512 chunks per array, 2 per thread (rows 0..63, 64..127)
    const int r0c = tid >> 2, ck = tid & 3;
    const int r1c = r0c + 64;
    const uint32_t dst0 = swz(r0c, ck);
    const uint32_t dst1 = swz(r1c, ck);
    const size_t gA0o = (size_t)(row0 + r0c) * K1 + ck * 8;
    const size_t gA1o = (size_t)(row0 + r1c) * K1 + ck * 8;
    const size_t gB0o = (size_t)(col0 + r0c) * K1 + ck * 8;
    const size_t gB1o = (size_t)(col0 + r1c) * K1 + ck * 8;

    float acc[2][8][4];
    #pragma unroll
    for (int mt = 0; mt < 2; mt++)
        #pragma unroll
        for (int ni = 0; ni < 8; ni++)
            #pragma unroll
            for (int q = 0; q < 4; q++) acc[mt][ni][q] = 0.f;

    // prologue: stages 0..2
    #pragma unroll
    for (int p = 0; p < 3; p++) {
        uint32_t st = sb + p * 16384u;
        int kOff = kStart + p * 32;
        cpasync16(st +    0 + dst0, A0 + gA0o + kOff);
        cpasync16(st +    0 + dst1, A0 + gA1o + kOff);
        cpasync16(st + 8192 + dst0, B0 + gB0o + kOff);
        cpasync16(st + 8192 + dst1, B0 + gB1o + kOff);
        CP_COMMIT();
    }

    int sIdx = 0;
    for (int it = 0; it < KIT1; it++) {
        CP_WAIT2();
        __syncthreads();

        if (it + 3 < KIT1) {
            int pIdx = (sIdx + 3) & 3;
            uint32_t st = sb + pIdx * 16384u;
            int kOff = kStart + (it + 3) * 32;
            cpasync16(st +    0 + dst0, A0 + gA0o + kOff);
            cpasync16(st +    0 + dst1, A0 + gA1o + kOff);
            cpasync16(st + 8192 + dst0, B0 + gB0o + kOff);
            cpasync16(st + 8192 + dst1, B0 + gB1o + kOff);
        }
        CP_COMMIT();

        const uint32_t st = sb + sIdx * 16384u;
        #pragma unroll
        for (int ksub = 0; ksub < 2; ksub++) {
            const int ckl = ksub*2 + (lane >> 4);
            uint32_t ah[2][4];
            #pragma unroll
            for (int mt = 0; mt < 2; mt++) {
                int row = warp_m*32 + mt*16 + (lane & 15);
                LDSM4(ah[mt], st + swz(row, ckl));
            }
            #pragma unroll
            for (int ni2 = 0; ni2 < 4; ni2++) {
                int row = warp_n*64 + ni2*16 + (lane & 15);
                uint32_t bh[4];
                LDSM4(bh, st + 8192 + swz(row, ckl));
                #pragma unroll
                for (int h = 0; h < 2; h++) {
                    const int ni = ni2*2 + h;
                    #pragma unroll
                    for (int mt = 0; mt < 2; mt++)
                        mma_f16(acc[mt][ni], ah[mt], bh[h], bh[2+h]);
                }
            }
        }
        sIdx = (sIdx + 1) & 3;
    }

    float* Cb = C + (size_t)blockIdx.z * ((size_t)M1 * N1);
    #pragma unroll
    for (int mt = 0; mt < 2; mt++) {
        int r_0 = row0 + warp_m*32 + mt*16 + g;
        int r_1 = r_0 + 8;
        #pragma unroll
        for (int ni = 0; ni < 8; ni++) {
            int cc = col0 + warp_n*64 + ni*8 + t4*2;
            if (r_0 < M1)
                *(float2*)(Cb + (size_t)r_0*N1 + cc) =
                    make_float2(acc[mt][ni][0], acc[mt][ni][1]);
            if (r_1 < M1)
                *(float2*)(Cb + (size_t)r_1*N1 + cc) =
                    make_float2(acc[mt][ni][2], acc[mt][ni][3]);
        }
    }
}

// ---------------- G2 GEMM (R14 known-good): CTA 64x128, occ 3 ----------
__global__ void __launch_bounds__(256, 3)
gemm_mma(const __half* __restrict__ A0, const __half* __restrict__ B0,
         int kIters, size_t aStride, size_t bStride,
         int rdiv, int rmul,
         float* __restrict__ C, int ldc, size_t cSplit) {
    extern __shared__ char smem[];
    const uint32_t sb = smem_u32(smem);
    const int tid = threadIdx.x;
    const int lane = tid & 31, wid = tid >> 5;
    const int warp_m = wid & 1, warp_n = wid >> 1;
    const int g = lane >> 2, t4 = lane & 3;
    const int row0 = blockIdx.y * 64;
    const int col0 = blockIdx.x * 128;
    const int kStart = blockIdx.z * kIters * 32;

    const int rA = tid >> 2, ckA = tid & 3;
    const uint32_t dstA = swz(rA, ckA);
    const int grA = row0 + rA;
    const size_t roffA = (size_t)((grA / rdiv) * rmul + (grA % rdiv)) * aStride
                       + (size_t)(ckA * 8);
    const int rB0 = tid >> 2;
    const int rB1 = rB0 + 64;
    const uint32_t dstB0 = swz(rB0, ckA);
    const uint32_t dstB1 = swz(rB1, ckA);
    const size_t goffB0 = (size_t)(col0 + rB0) * bStride + (size_t)(ckA * 8);
    const size_t goffB1 = (size_t)(col0 + rB1) * bStride + (size_t)(ckA * 8);

    float acc[2][4][4];
    #pragma unroll
    for (int mt = 0; mt < 2; mt++)
        #pragma unroll
        for (int ni = 0; ni < 4; ni++)
            #pragma unroll
            for (int q = 0; q < 4; q++) acc[mt][ni][q] = 0.f;

    #pragma unroll
    for (int p = 0; p < 3; p++) {
        uint32_t st = sb + p * 12288u;
        int kOff = kStart + p * 32;
        cpasync16(st +    0 + dstA, A0 + roffA + kOff);
        cpasync16(st + 4096 + dstB0, B0 + goffB0 + kOff);
        cpasync16(st + 4096 + dstB1, B0 + goffB1 + kOff);
        CP_COMMIT();
    }

    int sIdx = 0;
    for (int it = 0; it < kIters; it++) {
        CP_WAIT2();
        __syncthreads();

        if (it + 3 < kIters) {
            int pIdx = (sIdx + 3) & 3;
            uint32_t st = sb + pIdx * 12288u;
            int kOff = kStart + (it + 3) * 32;
            cpasync16(st +    0 + dstA, A0 + roffA + kOff);
            cpasync16(st + 4096 + dstB0, B0 + goffB0 + kOff);
            cpasync16(st + 4096 + dstB1, B0 + goffB1 + kOff);
        }
        CP_COMMIT();

        const uint32_t st = sb + sIdx * 12288u;
        #pragma unroll
        for (int ksub = 0; ksub < 2; ksub++) {
            const int ckl = ksub*2 + (lane >> 4);
            uint32_t ah[2][4];
            #pragma unroll
            for (int mt = 0; mt < 2; mt++) {
                int row = warp_m*32 + mt*16 + (lane & 15);
                LDSM4(ah[mt], st + swz(row, ckl));
            }
            #pragma unroll
            for (int ni2 = 0; ni2 < 2; ni2++) {
                int row = warp_n*32 + ni2*16 + (lane & 15);
                uint32_t bh[4];
                LDSM4(bh, st + 4096 + swz(row, ckl));
                #pragma unroll
                for (int h = 0; h < 2; h++) {
                    const int ni = ni2*2 + h;
                    #pragma unroll
                    for (int mt = 0; mt < 2; mt++)
                        mma_f16(acc[mt][ni], ah[mt], bh[h], bh[2+h]);
                }
            }
        }
        sIdx = (sIdx + 1) & 3;
    }

    float* Cb = C + (size_t)blockIdx.z * cSplit;
    #pragma unroll
    for (int mt = 0; mt < 2; mt++) {
        int r_0 = row0 + warp_m*32 + mt*16 + g;
        int r_1 = r_0 + 8;
        #pragma unroll
        for (int ni = 0; ni < 4; ni++) {
            int cc = col0 + warp_n*32 + ni*8 + t4*2;
            *(float2*)(Cb + (size_t)r_0*ldc + cc) =
                make_float2(acc[mt][ni][0], acc[mt][ni][1]);
            *(float2*)(Cb + (size_t)r_1*ldc + cc) =
                make_float2(acc[mt][ni][2], acc[mt][ni][3]);
        }
    }
}

// ---------------- combine split-K P + depth taps + bias + relu -> y -----
__global__ void combine_kernel(const float* __restrict__ b1a) {
    int bid = blockIdx.x;           // n*5 + d
    int n = bid / 5, d = bid % 5;
    __shared__ int mm[3];
    if (threadIdx.x < 3) {
        int t = d + threadIdx.x - 1;
        mm[threadIdx.x] = (t >= 0 && t < 5) ? g_map[n*5 + t] : -1;
    }
    __syncthreads();
    const size_t PS = (size_t)M1 * N1;
    for (int idx = threadIdx.x; idx < 9*512; idx += blockDim.x) {
        int sp = idx >> 9, co = idx & 511;
        float acc = b1a[co];
        #pragma unroll
        for (int kd = 0; kd < 3; kd++) {
            int m = mm[kd];
            if (m >= 0) {
                size_t o = ((size_t)(m*9 + sp))*N1 + kd*512 + co;
                #pragma unroll
                for (int z = 0; z < SPLIT1; z++)
                    acc += g_P[(size_t)z*PS + o];
            }
        }
        g_yh[(size_t)bid*4608 + idx] = __float2half(fmaxf(acc, 0.f));
    }
}

// ---------------- reduce split-K + bias/relu/max/FC ------------
__global__ void maxfc_kernel(const float* __restrict__ b1b,
                             const float* __restrict__ fcw,
                             const float* __restrict__ fcb,
                             float* __restrict__ out) {
    int n = blockIdx.x;
    __shared__ float z[256];
    int c = threadIdx.x;
    float v = -3.4e38f;
    #pragma unroll
    for (int dd = 0; dd < 3; dd++) {
        float s = 0.f;
        #pragma unroll
        for (int zz = 0; zz < SPLIT2; zz++)
            s += g_C2p[(size_t)zz*M2*N2 + (size_t)(n*3 + dd)*N2 + c];
        v = fmaxf(v, s);
    }
    z[c] = fmaxf(v + b1b[c], 0.f);
    __syncthreads();
    int warp = threadIdx.x >> 5, lane = threadIdx.x & 31;
    for (int j = warp; j < NB; j += 8) {
        float s = 0.f;
        #pragma unroll
        for (int q = 0; q < 8; q++)
            s += z[lane + q*32] * fcw[j*256 + lane + q*32];
        #pragma unroll
        for (int off = 16; off; off >>= 1)
            s += __shfl_xor_sync(0xffffffffu, s, off);
        if (lane == 0) out[n*NB + j] = s + fcb[j];
    }
}

// ---------------- launch ----------------
extern "C" void kernel_launch(void* const* d_in, const int* in_sizes, int n_in,
                              void* d_out, int out_size) {
    const float* fmaps = (const float*)d_in[0];
    const float* boxes = (const float*)d_in[1];
    const int*   pids  = (const int*)d_in[2];
    const float* w1a   = (const float*)d_in[3];
    const float* b1a   = (const float*)d_in[4];
    const float* w1b   = (const float*)d_in[5];
    const float* b1b   = (const float*)d_in[6];
    const float* fcw   = (const float*)d_in[7];
    const float* fcb   = (const float*)d_in[8];
    float* out = (float*)d_out;

    __half *pA0, *pB1, *pYh, *pB2;
    float *pP, *pC2p;
    cudaGetSymbolAddress((void**)&pA0, g_A0);
    cudaGetSymbolAddress((void**)&pB1, g_B1);
    cudaGetSymbolAddress((void**)&pYh, g_yh);
    cudaGetSymbolAddress((void**)&pB2, g_B2);
    cudaGetSymbolAddress((void**)&pP,  g_P);
    cudaGetSymbolAddress((void**)&pC2p, g_C2p);

    cudaFuncSetAttribute(gemm_g1,  cudaFuncAttributeMaxDynamicSharedMemorySize, 65536);
    cudaFuncSetAttribute(gemm_mma, cudaFuncAttributeMaxDynamicSharedMemorySize, 49152);
    cudaFuncSetAttribute(prep_all, cudaFuncAttributeMaxDynamicSharedMemorySize, 55296);

    // fused prep: roi+im2col | w1a | w1b | map — all independent
    prep_all<<<961, 256, 55296>>>(fmaps, boxes, pids, w1a, w1b);

    // G1 split-K=4: P[z][1728x1536] = A[1792x9216] * B[1536x9216]^T
    gemm_g1<<<dim3(N1/128, M1P/128, SPLIT1), 256, 65536>>>(pA0, pB1, pP);

    combine_kernel<<<NBOX*5, 256>>>(b1a);

    // G2 split-K=16: C2p[z][576x256] = y * B2^T, row remap (r/3)*5 + r%3
    gemm_mma<<<dim3(N2/128, M2/64, SPLIT2), 256, 49152>>>(
        pYh, pB2, KIT2, 4608, K2, 3, 5, pC2p, N2, (size_t)M2*N2);

    maxfc_kernel<<<NBOX, 256>>>(b1b, fcw, fcb, out);
}

// round 16
// speedup vs baseline: 1.2650x; 1.2650x over previous
#include <cuda_runtime.h>
#include <cuda_fp16.h>
#include <cstdint>

// ---------------- problem constants ----------------
#define F_    32
#define B_    6
#define C_    1024
#define HF    14
#define NB    27
#define T_    5
#define OUTP  3
#define SPAT  9
#define NBOX  (F_*B_)           // 192
#define K1    (C_*SPAT)         // 9216
#define N1    (3*512)           // 1536
#define M1    (NBOX*SPAT)       // 1728
#define K2    (512*27)          // 13824
#define M2    (NBOX*3)          // 576 = 9*64
#define N2    256
#define SPLIT1 3
#define SPLIT2 16
#define KIT2  27                // 13824/16/32

// ---------------- scratch ----------------
__device__ int   g_map[NBOX*T_];
__device__ __align__(16) __half g_roiR[(size_t)SPAT*NBOX*C_];  // [t][slice][ci]
__device__ __align__(16) __half g_B1[(size_t)N1*K1];   // w1a [n][k=tap*1024+ci]
__device__ float g_P [(size_t)SPLIT1*M1*N1];           // G1 tap-split partials
__device__ __align__(16) __half g_yh[(size_t)NBOX*5*4608];
__device__ __align__(16) __half g_B2[(size_t)N2*K2];   // w1b [n][k] fp16
__device__ float g_C2p[(size_t)SPLIT2*M2*N2];

// valid (t, tap) per output sp: entry = t | (tap<<4), padded with 0
__constant__ int c_tap[9][9] = {
    {0x40,0x51,0x73,0x84,0,0,0,0,0},
    {0x30,0x41,0x52,0x63,0x74,0x85,0,0,0},
    {0x31,0x42,0x64,0x75,0,0,0,0,0},
    {0x10,0x21,0x43,0x54,0x76,0x87,0,0,0},
    {0x00,0x11,0x22,0x33,0x44,0x55,0x66,0x77,0x88},
    {0x01,0x12,0x34,0x45,0x67,0x78,0,0,0},
    {0x13,0x24,0x46,0x57,0,0,0,0,0},
    {0x03,0x14,0x25,0x36,0x47,0x58,0,0,0},
    {0x04,0x15,0x37,0x48,0,0,0,0,0}
};
__constant__ int c_nv[9] = {4,6,4,6,9,6,4,6,4};

// ---------------- helpers ----------------
__device__ __forceinline__ void cpasync16(uint32_t dst, const void* src) {
    asm volatile("cp.async.cg.shared.global [%0], [%1], 16;"
                 :: "r"(dst), "l"(__cvta_generic_to_global(src)) : "memory");
}
__device__ __forceinline__ uint32_t smem_u32(const void* p) {
    uint32_t a;
    asm("{ .reg .u64 t; cvta.to.shared.u64 t, %1; cvt.u32.u64 %0, t; }"
        : "=r"(a) : "l"(p));
    return a;
}
#define CP_COMMIT() asm volatile("cp.async.commit_group;" ::: "memory")
#define CP_WAIT2()  asm volatile("cp.async.wait_group 2;" ::: "memory")
#define LDSM4(rr, a) asm volatile( \
    "ldmatrix.sync.aligned.m8n8.x4.shared.b16 {%0,%1,%2,%3}, [%4];" \
    : "=r"((rr)[0]),"=r"((rr)[1]),"=r"((rr)[2]),"=r"((rr)[3]) : "r"(a))
__device__ __forceinline__ void mma_f16(float* d, const uint32_t* a,
                                        uint32_t b0, uint32_t b1) {
    asm volatile(
        "mma.sync.aligned.m16n8k16.row.col.f32.f16.f16.f32 "
        "{%0,%1,%2,%3}, {%4,%5,%6,%7}, {%8,%9}, {%0,%1,%2,%3};"
        : "+f"(d[0]), "+f"(d[1]), "+f"(d[2]), "+f"(d[3])
        : "r"(a[0]), "r"(a[1]), "r"(a[2]), "r"(a[3]), "r"(b0), "r"(b1));
}
// conflict-free swizzle (R13): bank-quads of rows 0..7 = {0,4,1,5,2,6,3,7}
__device__ __forceinline__ uint32_t swz(int row, int ckl) {
    return (uint32_t)row*64u + (uint32_t)((ckl ^ ((row >> 1) & 3)) << 4);
}
__device__ __forceinline__ uint32_t pack2(__half a, __half b) {
    __half2 h2 = __halves2half2(a, b);
    return *(uint32_t*)&h2;
}

// ---------------- fused prep: roi->roiR | w1a | w1b | map ----------------
__global__ void __launch_bounds__(256)
prep_all(const float* __restrict__ fmaps, const float* __restrict__ boxes,
         const int* __restrict__ person_ids,
         const float* __restrict__ w1a, const float* __restrict__ w1b) {
    extern __shared__ char dyn[];
    const int bb = blockIdx.x;
    const int tid = threadIdx.x;

    if (bb < 192) {
        // ---------- ROI align -> roiR[t][slice][ci] ----------
        __half* sroi = (__half*)dyn;             // 9216 halves = 18KB
        __shared__ int   sy0[6], sy1[6], sx0[6], sx1[6];
        __shared__ float sly[6], slx[6];
        int nb = bb;
        int f  = nb / B_;
        if (tid < 12) {
            int  j   = tid % 6;
            bool isx = tid >= 6;
            float x1 = boxes[nb*4+0], y1 = boxes[nb*4+1];
            float x2 = boxes[nb*4+2], y2 = boxes[nb*4+3];
            float bw = fmaxf(x2 - x1, 1.0f) / (float)OUTP;
            float bh = fmaxf(y2 - y1, 1.0f) / (float)OUTP;
            float gj = (float)(j >> 1) + ((float)(j & 1) + 0.5f) * 0.5f;
            if (isx) {
                float xs  = x1 + bw * gj;
                float x0f = fminf(fmaxf(floorf(xs), 0.f), (float)(HF-1));
                float lx  = fminf(fmaxf(xs - x0f, 0.f), 1.f);
                int x0 = (int)x0f;
                sx0[j] = x0; sx1[j] = min(x0+1, HF-1); slx[j] = lx;
            } else {
                float ys  = y1 + bh * gj;
                float y0f = fminf(fmaxf(floorf(ys), 0.f), (float)(HF-1));
                float ly  = fminf(fmaxf(ys - y0f, 0.f), 1.f);
                int y0 = (int)y0f;
                sy0[j] = y0; sy1[j] = min(y0+1, HF-1); sly[j] = ly;
            }
        }
        __syncthreads();
        const float* base = fmaps + (size_t)f * C_ * HF * HF;
        for (int idx = tid; idx < C_*SPAT; idx += 256) {
            int c = idx / SPAT, o = idx % SPAT;
            int oi = o / 3, oj = o % 3;
            const float* fm = base + (size_t)c * HF * HF;
            float acc = 0.f;
            #pragma unroll
            for (int s = 0; s < 4; s++) {
                int jy = oi*2 + (s >> 1);
                int jx = oj*2 + (s & 1);
                float ly = sly[jy], lx = slx[jx];
                int y0 = sy0[jy], y1i = sy1[jy], x0 = sx0[jx], x1i = sx1[jx];
                acc += fm[y0*HF + x0]  * (1.f-ly)*(1.f-lx)
                     + fm[y0*HF + x1i] * (1.f-ly)*lx
                     + fm[y1i*HF + x0] * ly*(1.f-lx)
                     + fm[y1i*HF + x1i]* ly*lx;
            }
            sroi[idx] = __float2half(acc * 0.25f);
        }
        __syncthreads();
        #pragma unroll
        for (int o = 0; o < SPAT; o++) {
            uint32_t* d = (uint32_t*)(g_roiR + ((size_t)o*NBOX + nb) * C_);
            for (int cij = tid; cij < 512; cij += 256)
                d[cij] = pack2(sroi[(2*cij)*9 + o], sroi[(2*cij+1)*9 + o]);
        }
    } else if (bb < 704) {
        // ---------- w1a: [n=kd*512+co][k=tap*1024+ci] ----------
        __half* sh = (__half*)dyn;               // 27648 halves = 55296B
        int co = bb - 192;
        const float* src = w1a + (size_t)co * 27648;
        for (int i = tid; i < 27648; i += 256)
            sh[i] = __float2half(src[i]);        // conflict-free STS
        __syncthreads();
        #pragma unroll
        for (int kd = 0; kd < 3; kd++) {
            uint32_t* dst = (uint32_t*)(g_B1 + ((size_t)(kd*512 + co)) * 9216);
            const int kb = kd * 9;
            for (int jj = tid; jj < 4608; jj += 256) {
                int j = 2*jj;
                int tap = j >> 10, ci0 = j & 1023;
                dst[jj] = pack2(sh[ci0*27 + kb + tap],
                                sh[(ci0+1)*27 + kb + tap]);
            }
        }
    } else if (bb < 960) {
        // ---------- w1b: linear smem fp16, gather on read ----------
        __half* sh = (__half*)dyn;               // 13824 halves = 27648B
        int n = bb - 704;
        const float* src = w1b + (size_t)n * 13824;
        for (int i = tid; i < 13824; i += 256)
            sh[i] = __float2half(src[i]);
        __syncthreads();
        uint32_t* dst = (uint32_t*)(g_B2 + (size_t)n * 13824);
        for (int jj = tid; jj < 6912; jj += 256) {
            int j = 2*jj;
            int q = j >> 9, ci = j & 511;        // pairs never cross q
            dst[jj] = pack2(sh[ci*27 + q], sh[(ci+1)*27 + q]);
        }
    } else {
        // ---------- temporal index + person matching ----------
        int n = tid;
        if (n < NBOX) {
            int f = n / B_, b = n % B_;
            int pid = person_ids[f*B_ + b];
            int start = max(f - T_/2, 0);
            int end   = min(start + T_ - 1, F_ - 1);
            for (int t = 0; t < T_; t++) {
                int g = (int)((float)start + (float)(t*(end-start)) / (float)(T_-1));
                int m = -1;
                for (int bp = 0; bp < B_; bp++)
                    if (person_ids[g*B_ + bp] == pid) m = g*B_ + bp;
                g_map[n*T_ + t] = m;
            }
        }
    }
}

// ---------------- G1 tap-sparse GEMM: CTA 64 slices x 128 cols, occ 3 ------
// Each CTA owns output position sp (blockIdx.y/3) and a tap-list slice (z).
// A read directly from roiR[t][slice][ci]; k walks only valid taps (49/81).
__global__ void __launch_bounds__(256, 3)
gemm_g1tap(const __half* __restrict__ R, const __half* __restrict__ B0,
           float* __restrict__ C) {
    extern __shared__ char smem[];
    const uint32_t sb = smem_u32(smem);
    const int tid = threadIdx.x;
    const int lane = tid & 31, wid = tid >> 5;
    const int warp_m = wid & 1, warp_n = wid >> 1;
    const int g = lane >> 2, t4 = lane & 3;
    const int sp = blockIdx.y / 3;
    const int slice0 = (blockIdx.y % 3) * 64;
    const int col0 = blockIdx.x * 128;
    const int z = blockIdx.z;

    const int nv = c_nv[sp];
    int cnt, s0;
    if (nv == 9)      { cnt = 3; s0 = z * 3; }
    else if (nv == 6) { cnt = 2; s0 = z * 2; }
    else              { cnt = (z == 0) ? 2 : 1; s0 = (z == 0) ? 0 : (1 + z); }
    const int kIters = cnt * 32;

    const int rA = tid >> 2, ckA = tid & 3;
    const uint32_t dstA = swz(rA, ckA);
    const size_t aRow = (size_t)(slice0 + rA) * C_ + ckA * 8;
    const int rB0 = tid >> 2, rB1 = rB0 + 64;
    const uint32_t dstB0 = swz(rB0, ckA);
    const uint32_t dstB1 = swz(rB1, ckA);
    const size_t bRow0 = (size_t)(col0 + rB0) * K1 + ckA * 8;
    const size_t bRow1 = (size_t)(col0 + rB1) * K1 + ckA * 8;

    auto prefetch = [&](int it, uint32_t st) {
        int e = c_tap[sp][s0 + (it >> 5)];
        int t = e & 15, tap = e >> 4;
        int kk = (it & 31) << 5;
        cpasync16(st +    0 + dstA, R + (size_t)t * (NBOX*C_) + aRow + kk);
        cpasync16(st + 4096 + dstB0, B0 + bRow0 + (size_t)tap*C_ + kk);
        cpasync16(st + 4096 + dstB1, B0 + bRow1 + (size_t)tap*C_ + kk);
    };

    float acc[2][4][4];
    #pragma unroll
    for (int mt = 0; mt < 2; mt++)
        #pragma unroll
        for (int ni = 0; ni < 4; ni++)
            #pragma unroll
            for (int q = 0; q < 4; q++) acc[mt][ni][q] = 0.f;

    #pragma unroll
    for (int p = 0; p < 3; p++) {
        prefetch(p, sb + p * 12288u);
        CP_COMMIT();
    }

    int sIdx = 0;
    for (int it = 0; it < kIters; it++) {
        CP_WAIT2();
        __syncthreads();

        if (it + 3 < kIters)
            prefetch(it + 3, sb + ((sIdx + 3) & 3) * 12288u);
        CP_COMMIT();

        const uint32_t st = sb + sIdx * 12288u;
        #pragma unroll
        for (int ksub = 0; ksub < 2; ksub++) {
            const int ckl = ksub*2 + (lane >> 4);
            uint32_t ah[2][4];
            #pragma unroll
            for (int mt = 0; mt < 2; mt++) {
                int row = warp_m*32 + mt*16 + (lane & 15);
                LDSM4(ah[mt], st + swz(row, ckl));
            }
            #pragma unroll
            for (int ni2 = 0; ni2 < 2; ni2++) {
                int row = warp_n*32 + ni2*16 + (lane & 15);
                uint32_t bh[4];
                LDSM4(bh, st + 4096 + swz(row, ckl));
                #pragma unroll
                for (int h = 0; h < 2; h++) {
                    const int ni = ni2*2 + h;
                    #pragma unroll
                    for (int mt = 0; mt < 2; mt++)
                        mma_f16(acc[mt][ni], ah[mt], bh[h], bh[2+h]);
                }
            }
        }
        sIdx = (sIdx + 1) & 3;
    }

    float* Cb = C + (size_t)z * ((size_t)M1 * N1);
    #pragma unroll
    for (int mt = 0; mt < 2; mt++) {
        int s_0 = slice0 + warp_m*32 + mt*16 + g;   // slice
        int pr0 = s_0*9 + sp;                        // P row
        int pr1 = (s_0 + 8)*9 + sp;
        #pragma unroll
        for (int ni = 0; ni < 4; ni++) {
            int cc = col0 + warp_n*32 + ni*8 + t4*2;
            *(float2*)(Cb + (size_t)pr0*N1 + cc) =
                make_float2(acc[mt][ni][0], acc[mt][ni][1]);
            *(float2*)(Cb + (size_t)pr1*N1 + cc) =
                make_float2(acc[mt][ni][2], acc[mt][ni][3]);
        }
    }
}

// ---------------- G2 GEMM (R14 known-good): CTA 64x128, occ 3 ----------
__global__ void __launch_bounds__(256, 3)
gemm_mma(const __half* __restrict__ A0, const __half* __restrict__ B0,
         int kIters, size_t aStride, size_t bStride,
         int rdiv, int rmul,
         float* __restrict__ C, int ldc, size_t cSplit) {
    extern __shared__ char smem[];
    const uint32_t sb = smem_u32(smem);
    const int tid = threadIdx.x;
    const int lane = tid & 31, wid = tid >> 5;
    const int warp_m = wid & 1, warp_n = wid >> 1;
    const int g = lane >> 2, t4 = lane & 3;
    const int row0 = blockIdx.y * 64;
    const int col0 = blockIdx.x * 128;
    const int kStart = blockIdx.z * kIters * 32;

    const int rA = tid >> 2, ckA = tid & 3;
    const uint32_t dstA = swz(rA, ckA);
    const int grA = row0 + rA;
    const size_t roffA = (size_t)((grA / rdiv) * rmul + (grA % rdiv)) * aStride
                       + (size_t)(ckA * 8);
    const int rB0 = tid >> 2;
    const int rB1 = rB0 + 64;
    const uint32_t dstB0 = swz(rB0, ckA);
    const uint32_t dstB1 = swz(rB1, ckA);
    const size_t goffB0 = (size_t)(col0 + rB0) * bStride + (size_t)(ckA * 8);
    const size_t goffB1 = (size_t)(col0 + rB1) * bStride + (size_t)(ckA * 8);

    float acc[2][4][4];
    #pragma unroll
    for (int mt = 0; mt < 2; mt++)
        #pragma unroll
        for (int ni = 0; ni < 4; ni++)
            #pragma unroll
            for (int q = 0; q < 4; q++) acc[mt][ni][q] = 0.f;

    #pragma unroll
    for (int p = 0; p < 3; p++) {
        uint32_t st = sb + p * 12288u;
        int kOff = kStart + p * 32;
        cpasync16(st +    0 + dstA, A0 + roffA + kOff);
        cpasync16(st + 4096 + dstB0, B0 + goffB0 + kOff);
        cpasync16(st + 4096 + dstB1, B0 + goffB1 + kOff);
        CP_COMMIT();
    }

    int sIdx = 0;
    for (int it = 0; it < kIters; it++) {
        CP_WAIT2();
        __syncthreads();

        if (it + 3 < kIters) {
            int pIdx = (sIdx + 3) & 3;
            uint32_t st = sb + pIdx * 12288u;
            int kOff = kStart + (it + 3) * 32;
            cpasync16(st +    0 + dstA, A0 + roffA + kOff);
            cpasync16(st + 4096 + dstB0, B0 + goffB0 + kOff);
            cpasync16(st + 4096 + dstB1, B0 + goffB1 + kOff);
        }
        CP_COMMIT();

        const uint32_t st = sb + sIdx * 12288u;
        #pragma unroll
        for (int ksub = 0; ksub < 2; ksub++) {
            const int ckl = ksub*2 + (lane >> 4);
            uint32_t ah[2][4];
            #pragma unroll
            for (int mt = 0; mt < 2; mt++) {
                int row = warp_m*32 + mt*16 + (lane & 15);
                LDSM4(ah[mt], st + swz(row, ckl));
            }
            #pragma unroll
            for (int ni2 = 0; ni2 < 2; ni2++) {
                int row = warp_n*32 + ni2*16 + (lane & 15);
                uint32_t bh[4];
                LDSM4(bh, st + 4096 + swz(row, ckl));
                #pragma unroll
                for (int h = 0; h < 2; h++) {
                    const int ni = ni2*2 + h;
                    #pragma unroll
                    for (int mt = 0; mt < 2; mt++)
                        mma_f16(acc[mt][ni], ah[mt], bh[h], bh[2+h]);
                }
            }
        }
        sIdx = (sIdx + 1) & 3;
    }

    float* Cb = C + (size_t)blockIdx.z * cSplit;
    #pragma unroll
    for (int mt = 0; mt < 2; mt++) {
        int r_0 = row0 + warp_m*32 + mt*16 + g;
        int r_1 = r_0 + 8;
        #pragma unroll
        for (int ni = 0; ni < 4; ni++) {
            int cc = col0 + warp_n*32 + ni*8 + t4*2;
            *(float2*)(Cb + (size_t)r_0*ldc + cc) =
                make_float2(acc[mt][ni][0], acc[mt][ni][1]);
            *(float2*)(Cb + (size_t)r_1*ldc + cc) =
                make_float2(acc[mt][ni][2], acc[mt][ni][3]);
        }
    }
}

// ---------------- combine split P + depth taps + bias + relu -> y -----
__global__ void combine_kernel(const float* __restrict__ b1a) {
    int bid = blockIdx.x;           // n*5 + d
    int n = bid / 5, d = bid % 5;
    __shared__ int mm[3];
    if (threadIdx.x < 3) {
        int t = d + threadIdx.x - 1;
        mm[threadIdx.x] = (t >= 0 && t < 5) ? g_map[n*5 + t] : -1;
    }
    __syncthreads();
    const size_t PS = (size_t)M1 * N1;
    for (int idx = threadIdx.x; idx < 9*512; idx += blockDim.x) {
        int sp = idx >> 9, co = idx & 511;
        float acc = b1a[co];
        #pragma unroll
        for (int kd = 0; kd < 3; kd++) {
            int m = mm[kd];
            if (m >= 0) {
                size_t o = ((size_t)(m*9 + sp))*N1 + kd*512 + co;
                #pragma unroll
                for (int z = 0; z < SPLIT1; z++)
                    acc += g_P[(size_t)z*PS + o];
            }
        }
        g_yh[(size_t)bid*4608 + idx] = __float2half(fmaxf(acc, 0.f));
    }
}

// ---------------- reduce split-K + bias/relu/max/FC ------------
__global__ void maxfc_kernel(const float* __restrict__ b1b,
                             const float* __restrict__ fcw,
                             const float* __restrict__ fcb,
                             float* __restrict__ out) {
    int n = blockIdx.x;
    __shared__ float z[256];
    int c = threadIdx.x;
    float v = -3.4e38f;
    #pragma unroll
    for (int dd = 0; dd < 3; dd++) {
        float s = 0.f;
        #pragma unroll
        for (int zz = 0; zz < SPLIT2; zz++)
            s += g_C2p[(size_t)zz*M2*N2 + (size_t)(n*3 + dd)*N2 + c];
        v = fmaxf(v, s);
    }
    z[c] = fmaxf(v + b1b[c], 0.f);
    __syncthreads();
    int warp = threadIdx.x >> 5, lane = threadIdx.x & 31;
    for (int j = warp; j < NB; j += 8) {
        float s = 0.f;
        #pragma unroll
        for (int q = 0; q < 8; q++)
            s += z[lane + q*32] * fcw[j*256 + lane + q*32];
        #pragma unroll
        for (int off = 16; off; off >>= 1)
            s += __shfl_xor_sync(0xffffffffu, s, off);
        if (lane == 0) out[n*NB + j] = s + fcb[j];
    }
}

// ---------------- launch ----------------
extern "C" void kernel_launch(void* const* d_in, const int* in_sizes, int n_in,
                              void* d_out, int out_size) {
    const float* fmaps = (const float*)d_in[0];
    const float* boxes = (const float*)d_in[1];
    const int*   pids  = (const int*)d_in[2];
    const float* w1a   = (const float*)d_in[3];
    const float* b1a   = (const float*)d_in[4];
    const float* w1b   = (const float*)d_in[5];
    const float* b1b   = (const float*)d_in[6];
    const float* fcw   = (const float*)d_in[7];
    const float* fcb   = (const float*)d_in[8];
    float* out = (float*)d_out;

    __half *pR, *pB1, *pYh, *pB2;
    float *pP, *pC2p;
    cudaGetSymbolAddress((void**)&pR,  g_roiR);
    cudaGetSymbolAddress((void**)&pB1, g_B1);
    cudaGetSymbolAddress((void**)&pYh, g_yh);
    cudaGetSymbolAddress((void**)&pB2, g_B2);
    cudaGetSymbolAddress((void**)&pP,  g_P);
    cudaGetSymbolAddress((void**)&pC2p, g_C2p);

    cudaFuncSetAttribute(gemm_g1tap, cudaFuncAttributeMaxDynamicSharedMemorySize, 49152);
    cudaFuncSetAttribute(gemm_mma,   cudaFuncAttributeMaxDynamicSharedMemorySize, 49152);
    cudaFuncSetAttribute(prep_all,   cudaFuncAttributeMaxDynamicSharedMemorySize, 55296);

    // fused prep: roi->roiR | w1a | w1b | map — all independent
    prep_all<<<961, 256, 55296>>>(fmaps, boxes, pids, w1a, w1b);

    // G1 tap-sparse: P[z][1728x1536] += roiR x B1 over valid taps only
    gemm_g1tap<<<dim3(N1/128, 27, SPLIT1), 256, 49152>>>(pR, pB1, pP);

    combine_kernel<<<NBOX*5, 256>>>(b1a);

    // G2 split-K=16: C2p[z][576x256] = y * B2^T, row remap (r/3)*5 + r%3
    gemm_mma<<<dim3(N2/128, M2/64, SPLIT2), 256, 49152>>>(
        pYh, pB2, KIT2, 4608, K2, 3, 5, pC2p, N2, (size_t)M2*N2);

    maxfc_kernel<<<NBOX, 256>>>(b1b, fcw, fcb, out);
}

// round 17
// speedup vs baseline: 1.2737x; 1.0069x over previous
#include <cuda_runtime.h>
#include <cuda_fp16.h>
#include <cstdint>

// ---------------- problem constants ----------------
#define F_    32
#define B_    6
#define C_    1024
#define HF    14
#define NB    27
#define T_    5
#define OUTP  3
#define SPAT  9
#define NBOX  (F_*B_)           // 192
#define K1    (C_*SPAT)         // 9216
#define N1    (3*512)           // 1536
#define M1    (NBOX*SPAT)       // 1728
#define K2    (512*27)          // 13824
#define M2    (NBOX*3)          // 576 = 9*64
#define N2    256
#define SPLIT1 3
#define SPLIT2 16
#define KIT2  27                // 13824/16/32

// ---------------- scratch ----------------
__device__ int   g_map[NBOX*T_];
__device__ __align__(16) __half g_roiR[(size_t)SPAT*NBOX*C_];  // [t][slice][ci]
__device__ __align__(16) __half g_B1[(size_t)N1*K1];   // w1a [n][k=tap*1024+ci]
__device__ __align__(16) __half g_P [(size_t)SPLIT1*M1*N1];  // fp16 partials
__device__ __align__(16) __half g_yh[(size_t)NBOX*5*4608];
__device__ __align__(16) __half g_B2[(size_t)N2*K2];   // w1b [n][k] fp16
__device__ float g_C2p[(size_t)SPLIT2*M2*N2];

// valid (t, tap) per output sp: entry = t | (tap<<4), padded with 0
__constant__ int c_tap[9][9] = {
    {0x40,0x51,0x73,0x84,0,0,0,0,0},
    {0x30,0x41,0x52,0x63,0x74,0x85,0,0,0},
    {0x31,0x42,0x64,0x75,0,0,0,0,0},
    {0x10,0x21,0x43,0x54,0x76,0x87,0,0,0},
    {0x00,0x11,0x22,0x33,0x44,0x55,0x66,0x77,0x88},
    {0x01,0x12,0x34,0x45,0x67,0x78,0,0,0},
    {0x13,0x24,0x46,0x57,0,0,0,0,0},
    {0x03,0x14,0x25,0x36,0x47,0x58,0,0,0},
    {0x04,0x15,0x37,0x48,0,0,0,0,0}
};
__constant__ int c_nv[9] = {4,6,4,6,9,6,4,6,4};

// ---------------- helpers ----------------
__device__ __forceinline__ void cpasync16(uint32_t dst, const void* src) {
    asm volatile("cp.async.cg.shared.global [%0], [%1], 16;"
                 :: "r"(dst), "l"(__cvta_generic_to_global(src)) : "memory");
}
__device__ __forceinline__ uint32_t smem_u32(const void* p) {
    uint32_t a;
    asm("{ .reg .u64 t; cvta.to.shared.u64 t, %1; cvt.u32.u64 %0, t; }"
        : "=r"(a) : "l"(p));
    return a;
}
#define CP_COMMIT() asm volatile("cp.async.commit_group;" ::: "memory")
#define CP_WAIT2()  asm volatile("cp.async.wait_group 2;" ::: "memory")
#define CP_WAIT1()  asm volatile("cp.async.wait_group 1;" ::: "memory")
#define LDSM4(rr, a) asm volatile( \
    "ldmatrix.sync.aligned.m8n8.x4.shared.b16 {%0,%1,%2,%3}, [%4];" \
    : "=r"((rr)[0]),"=r"((rr)[1]),"=r"((rr)[2]),"=r"((rr)[3]) : "r"(a))
__device__ __forceinline__ void mma_f16(float* d, const uint32_t* a,
                                        uint32_t b0, uint32_t b1) {
    asm volatile(
        "mma.sync.aligned.m16n8k16.row.col.f32.f16.f16.f32 "
        "{%0,%1,%2,%3}, {%4,%5,%6,%7}, {%8,%9}, {%0,%1,%2,%3};"
        : "+f"(d[0]), "+f"(d[1]), "+f"(d[2]), "+f"(d[3])
        : "r"(a[0]), "r"(a[1]), "r"(a[2]), "r"(a[3]), "r"(b0), "r"(b1));
}
// conflict-free swizzle (R13): bank-quads of rows 0..7 = {0,4,1,5,2,6,3,7}
__device__ __forceinline__ uint32_t swz(int row, int ckl) {
    return (uint32_t)row*64u + (uint32_t)((ckl ^ ((row >> 1) & 3)) << 4);
}
__device__ __forceinline__ uint32_t pack2(__half a, __half b) {
    __half2 h2 = __halves2half2(a, b);
    return *(uint32_t*)&h2;
}
__device__ __forceinline__ uint32_t packf2(float a, float b) {
    __half2 h2 = __floats2half2_rn(a, b);
    return *(uint32_t*)&h2;
}

// ---------------- fused prep: roi->roiR | w1a | w1b | map ----------------
__global__ void __launch_bounds__(256)
prep_all(const float* __restrict__ fmaps, const float* __restrict__ boxes,
         const int* __restrict__ person_ids,
         const float* __restrict__ w1a, const float* __restrict__ w1b) {
    extern __shared__ char dyn[];
    const int bb = blockIdx.x;
    const int tid = threadIdx.x;

    if (bb < 192) {
        // ---------- ROI align -> roiR[t][slice][ci] ----------
        __half* sroi = (__half*)dyn;             // 9216 halves = 18KB
        __shared__ int   sy0[6], sy1[6], sx0[6], sx1[6];
        __shared__ float sly[6], slx[6];
        int nb = bb;
        int f  = nb / B_;
        if (tid < 12) {
            int  j   = tid % 6;
            bool isx = tid >= 6;
            float x1 = boxes[nb*4+0], y1 = boxes[nb*4+1];
            float x2 = boxes[nb*4+2], y2 = boxes[nb*4+3];
            float bw = fmaxf(x2 - x1, 1.0f) / (float)OUTP;
            float bh = fmaxf(y2 - y1, 1.0f) / (float)OUTP;
            float gj = (float)(j >> 1) + ((float)(j & 1) + 0.5f) * 0.5f;
            if (isx) {
                float xs  = x1 + bw * gj;
                float x0f = fminf(fmaxf(floorf(xs), 0.f), (float)(HF-1));
                float lx  = fminf(fmaxf(xs - x0f, 0.f), 1.f);
                int x0 = (int)x0f;
                sx0[j] = x0; sx1[j] = min(x0+1, HF-1); slx[j] = lx;
            } else {
                float ys  = y1 + bh * gj;
                float y0f = fminf(fmaxf(floorf(ys), 0.f), (float)(HF-1));
                float ly  = fminf(fmaxf(ys - y0f, 0.f), 1.f);
                int y0 = (int)y0f;
                sy0[j] = y0; sy1[j] = min(y0+1, HF-1); sly[j] = ly;
            }
        }
        __syncthreads();
        const float* base = fmaps + (size_t)f * C_ * HF * HF;
        for (int idx = tid; idx < C_*SPAT; idx += 256) {
            int c = idx / SPAT, o = idx % SPAT;
            int oi = o / 3, oj = o % 3;
            const float* fm = base + (size_t)c * HF * HF;
            float acc = 0.f;
            #pragma unroll
            for (int s = 0; s < 4; s++) {
                int jy = oi*2 + (s >> 1);
                int jx = oj*2 + (s & 1);
                float ly = sly[jy], lx = slx[jx];
                int y0 = sy0[jy], y1i = sy1[jy], x0 = sx0[jx], x1i = sx1[jx];
                acc += fm[y0*HF + x0]  * (1.f-ly)*(1.f-lx)
                     + fm[y0*HF + x1i] * (1.f-ly)*lx
                     + fm[y1i*HF + x0] * ly*(1.f-lx)
                     + fm[y1i*HF + x1i]* ly*lx;
            }
            sroi[idx] = __float2half(acc * 0.25f);
        }
        __syncthreads();
        #pragma unroll
        for (int o = 0; o < SPAT; o++) {
            uint32_t* d = (uint32_t*)(g_roiR + ((size_t)o*NBOX + nb) * C_);
            for (int cij = tid; cij < 512; cij += 256)
                d[cij] = pack2(sroi[(2*cij)*9 + o], sroi[(2*cij+1)*9 + o]);
        }
    } else if (bb < 704) {
        // ---------- w1a: [n=kd*512+co][k=tap*1024+ci] ----------
        __half* sh = (__half*)dyn;               // 27648 halves = 55296B
        int co = bb - 192;
        const float* src = w1a + (size_t)co * 27648;
        for (int i = tid; i < 27648; i += 256)
            sh[i] = __float2half(src[i]);        // conflict-free STS
        __syncthreads();
        #pragma unroll
        for (int kd = 0; kd < 3; kd++) {
            uint32_t* dst = (uint32_t*)(g_B1 + ((size_t)(kd*512 + co)) * 9216);
            const int kb = kd * 9;
            for (int jj = tid; jj < 4608; jj += 256) {
                int j = 2*jj;
                int tap = j >> 10, ci0 = j & 1023;
                dst[jj] = pack2(sh[ci0*27 + kb + tap],
                                sh[(ci0+1)*27 + kb + tap]);
            }
        }
    } else if (bb < 960) {
        // ---------- w1b: linear smem fp16, gather on read ----------
        __half* sh = (__half*)dyn;               // 13824 halves = 27648B
        int n = bb - 704;
        const float* src = w1b + (size_t)n * 13824;
        for (int i = tid; i < 13824; i += 256)
            sh[i] = __float2half(src[i]);
        __syncthreads();
        uint32_t* dst = (uint32_t*)(g_B2 + (size_t)n * 13824);
        for (int jj = tid; jj < 6912; jj += 256) {
            int j = 2*jj;
            int q = j >> 9, ci = j & 511;        // pairs never cross q
            dst[jj] = pack2(sh[ci*27 + q], sh[(ci+1)*27 + q]);
        }
    } else {
        // ---------- temporal index + person matching ----------
        int n = tid;
        if (n < NBOX) {
            int f = n / B_, b = n % B_;
            int pid = person_ids[f*B_ + b];
            int start = max(f - T_/2, 0);
            int end   = min(start + T_ - 1, F_ - 1);
            for (int t = 0; t < T_; t++) {
                int g = (int)((float)start + (float)(t*(end-start)) / (float)(T_-1));
                int m = -1;
                for (int bp = 0; bp < B_; bp++)
                    if (person_ids[g*B_ + bp] == pid) m = g*B_ + bp;
                g_map[n*T_ + t] = m;
            }
        }
    }
}

// ---------------- G1 tap-sparse GEMM: CTA 64x128, BK=64, 3-stage, occ 3 ----
// Stage = 24KB: two 12KB halves (A 4KB + B 8KB each, proven layout).
// Pipeline: wait -> barrier -> prefetch(it+2) -> compute (WAR fenced).
__global__ void __launch_bounds__(256, 3)
gemm_g1tap(const __half* __restrict__ R, const __half* __restrict__ B0,
           __half* __restrict__ C) {
    extern __shared__ char smem[];
    const uint32_t sb = smem_u32(smem);
    const int tid = threadIdx.x;
    const int lane = tid & 31, wid = tid >> 5;
    const int warp_m = wid & 1, warp_n = wid >> 1;
    const int g = lane >> 2, t4 = lane & 3;
    const int sp = blockIdx.y / 3;
    const int slice0 = (blockIdx.y % 3) * 64;
    const int col0 = blockIdx.x * 128;
    const int z = blockIdx.z;

    const int nv = c_nv[sp];
    int cnt, s0;
    if (nv == 9)      { cnt = 3; s0 = z * 3; }
    else if (nv == 6) { cnt = 2; s0 = z * 2; }
    else              { cnt = (z == 0) ? 2 : 1; s0 = (z == 0) ? 0 : (1 + z); }
    const int kIters = cnt * 16;     // 64-k units

    const int rA = tid >> 2, ckA = tid & 3;
    const uint32_t dstA = swz(rA, ckA);
    const size_t aRow = (size_t)(slice0 + rA) * C_ + ckA * 8;
    const int rB0 = tid >> 2, rB1 = rB0 + 64;
    const uint32_t dstB0 = swz(rB0, ckA);
    const uint32_t dstB1 = swz(rB1, ckA);
    const size_t bRow0 = (size_t)(col0 + rB0) * K1 + ckA * 8;
    const size_t bRow1 = (size_t)(col0 + rB1) * K1 + ckA * 8;

    auto prefetch = [&](int it, uint32_t st) {
        int e = c_tap[sp][s0 + (it >> 4)];
        int t = e & 15, tap = e >> 4;
        int kk = (it & 15) << 6;     // 64 halves per iter
        #pragma unroll
        for (int h = 0; h < 2; h++) {
            uint32_t hb = st + h * 12288u;
            int ko = kk + h * 32;
            cpasync16(hb +    0 + dstA, R + (size_t)t * (NBOX*C_) + aRow + ko);
            cpasync16(hb + 4096 + dstB0, B0 + bRow0 + (size_t)tap*C_ + ko);
            cpasync16(hb + 4096 + dstB1, B0 + bRow1 + (size_t)tap*C_ + ko);
        }
    };

    float acc[2][4][4];
    #pragma unroll
    for (int mt = 0; mt < 2; mt++)
        #pragma unroll
        for (int ni = 0; ni < 4; ni++)
            #pragma unroll
            for (int q = 0; q < 4; q++) acc[mt][ni][q] = 0.f;

    prefetch(0, sb);            CP_COMMIT();
    prefetch(1, sb + 24576u);   CP_COMMIT();

    int sIdx = 0;
    for (int it = 0; it < kIters; it++) {
        CP_WAIT1();            // stage sIdx landed (1 newer pending)
        __syncthreads();       // fences prior reads of the stage we overwrite

        if (it + 2 < kIters) {
            int pIdx = sIdx + 2; if (pIdx >= 3) pIdx -= 3;
            prefetch(it + 2, sb + (uint32_t)pIdx * 24576u);
        }
        CP_COMMIT();

        const uint32_t stage = sb + (uint32_t)sIdx * 24576u;
        #pragma unroll
        for (int h = 0; h < 2; h++) {
            const uint32_t st = stage + h * 12288u;
            #pragma unroll
            for (int ksub = 0; ksub < 2; ksub++) {
                const int ckl = ksub*2 + (lane >> 4);
                uint32_t ah[2][4];
                #pragma unroll
                for (int mt = 0; mt < 2; mt++) {
                    int row = warp_m*32 + mt*16 + (lane & 15);
                    LDSM4(ah[mt], st + swz(row, ckl));
                }
                #pragma unroll
                for (int ni2 = 0; ni2 < 2; ni2++) {
                    int row = warp_n*32 + ni2*16 + (lane & 15);
                    uint32_t bh[4];
                    LDSM4(bh, st + 4096 + swz(row, ckl));
                    #pragma unroll
                    for (int hh = 0; hh < 2; hh++) {
                        const int ni = ni2*2 + hh;
                        #pragma unroll
                        for (int mt = 0; mt < 2; mt++)
                            mma_f16(acc[mt][ni], ah[mt], bh[hh], bh[2+hh]);
                    }
                }
            }
        }
        if (++sIdx == 3) sIdx = 0;
    }

    __half* Cb = C + (size_t)z * ((size_t)M1 * N1);
    #pragma unroll
    for (int mt = 0; mt < 2; mt++) {
        int s_0 = slice0 + warp_m*32 + mt*16 + g;   // slice
        int pr0 = s_0*9 + sp;                        // P row
        int pr1 = (s_0 + 8)*9 + sp;
        #pragma unroll
        for (int ni = 0; ni < 4; ni++) {
            int cc = col0 + warp_n*32 + ni*8 + t4*2;
            *(uint32_t*)(Cb + (size_t)pr0*N1 + cc) =
                packf2(acc[mt][ni][0], acc[mt][ni][1]);
            *(uint32_t*)(Cb + (size_t)pr1*N1 + cc) =
                packf2(acc[mt][ni][2], acc[mt][ni][3]);
        }
    }
}

// ---------------- G2 GEMM (R14 known-good): CTA 64x128, BK=32, occ 3 -------
__global__ void __launch_bounds__(256, 3)
gemm_mma(const __half* __restrict__ A0, const __half* __restrict__ B0,
         int kIters, size_t aStride, size_t bStride,
         int rdiv, int rmul,
         float* __restrict__ C, int ldc, size_t cSplit) {
    extern __shared__ char smem[];
    const uint32_t sb = smem_u32(smem);
    const int tid = threadIdx.x;
    const int lane = tid & 31, wid = tid >> 5;
    const int warp_m = wid & 1, warp_n = wid >> 1;
    const int g = lane >> 2, t4 = lane & 3;
    const int row0 = blockIdx.y * 64;
    const int col0 = blockIdx.x * 128;
    const int kStart = blockIdx.z * kIters * 32;

    const int rA = tid >> 2, ckA = tid & 3;
    const uint32_t dstA = swz(rA, ckA);
    const int grA = row0 + rA;
    const size_t roffA = (size_t)((grA / rdiv) * rmul + (grA % rdiv)) * aStride
                       + (size_t)(ckA * 8);
    const int rB0 = tid >> 2;
    const int rB1 = rB0 + 64;
    const uint32_t dstB0 = swz(rB0, ckA);
    const uint32_t dstB1 = swz(rB1, ckA);
    const size_t goffB0 = (size_t)(col0 + rB0) * bStride + (size_t)(ckA * 8);
    const size_t goffB1 = (size_t)(col0 + rB1) * bStride + (size_t)(ckA * 8);

    float acc[2][4][4];
    #pragma unroll
    for (int mt = 0; mt < 2; mt++)
        #pragma unroll
        for (int ni = 0; ni < 4; ni++)
            #pragma unroll
            for (int q = 0; q < 4; q++) acc[mt][ni][q] = 0.f;

    #pragma unroll
    for (int p = 0; p < 3; p++) {
        uint32_t st = sb + p * 12288u;
        int kOff = kStart + p * 32;
        cpasync16(st +    0 + dstA, A0 + roffA + kOff);
        cpasync16(st + 4096 + dstB0, B0 + goffB0 + kOff);
        cpasync16(st + 4096 + dstB1, B0 + goffB1 + kOff);
        CP_COMMIT();
    }

    int sIdx = 0;
    for (int it = 0; it < kIters; it++) {
        CP_WAIT2();
        __syncthreads();

        if (it + 3 < kIters) {
            int pIdx = (sIdx + 3) & 3;
            uint32_t st = sb + pIdx * 12288u;
            int kOff = kStart + (it + 3) * 32;
            cpasync16(st +    0 + dstA, A0 + roffA + kOff);
            cpasync16(st + 4096 + dstB0, B0 + goffB0 + kOff);
            cpasync16(st + 4096 + dstB1, B0 + goffB1 + kOff);
        }
        CP_COMMIT();

        const uint32_t st = sb + sIdx * 12288u;
        #pragma unroll
        for (int ksub = 0; ksub < 2; ksub++) {
            const int ckl = ksub*2 + (lane >> 4);
            uint32_t ah[2][4];
            #pragma unroll
            for (int mt = 0; mt < 2; mt++) {
                int row = warp_m*32 + mt*16 + (lane & 15);
                LDSM4(ah[mt], st + swz(row, ckl));
            }
            #pragma unroll
            for (int ni2 = 0; ni2 < 2; ni2++) {
                int row = warp_n*32 + ni2*16 + (lane & 15);
                uint32_t bh[4];
                LDSM4(bh, st + 4096 + swz(row, ckl));
                #pragma unroll
                for (int h = 0; h < 2; h++) {
                    const int ni = ni2*2 + h;
                    #pragma unroll
                    for (int mt = 0; mt < 2; mt++)
                        mma_f16(acc[mt][ni], ah[mt], bh[h], bh[2+h]);
                }
            }
        }
        sIdx = (sIdx + 1) & 3;
    }

    float* Cb = C + (size_t)blockIdx.z * cSplit;
    #pragma unroll
    for (int mt = 0; mt < 2; mt++) {
        int r_0 = row0 + warp_m*32 + mt*16 + g;
        int r_1 = r_0 + 8;
        #pragma unroll
        for (int ni = 0; ni < 4; ni++) {
            int cc = col0 + warp_n*32 + ni*8 + t4*2;
            *(float2*)(Cb + (size_t)r_0*ldc + cc) =
                make_float2(acc[mt][ni][0], acc[mt][ni][1]);
            *(float2*)(Cb + (size_t)r_1*ldc + cc) =
                make_float2(acc[mt][ni][2], acc[mt][ni][3]);
        }
    }
}

// ---------------- combine split P (fp16) + depth taps + bias + relu -> y ---
__global__ void combine_kernel(const float* __restrict__ b1a) {
    int bid = blockIdx.x;           // n*5 + d
    int n = bid / 5, d = bid % 5;
    __shared__ int mm[3];
    if (threadIdx.x < 3) {
        int t = d + threadIdx.x - 1;
        mm[threadIdx.x] = (t >= 0 && t < 5) ? g_map[n*5 + t] : -1;
    }
    __syncthreads();
    const size_t PS = (size_t)M1 * N1;
    for (int idx = threadIdx.x; idx < 9*512; idx += blockDim.x) {
        int sp = idx >> 9, co = idx & 511;
        float acc = b1a[co];
        #pragma unroll
        for (int kd = 0; kd < 3; kd++) {
            int m = mm[kd];
            if (m >= 0) {
                size_t o = ((size_t)(m*9 + sp))*N1 + kd*512 + co;
                #pragma unroll
                for (int z = 0; z < SPLIT1; z++)
                    acc += __half2float(g_P[(size_t)z*PS + o]);
            }
        }
        g_yh[(size_t)bid*4608 + idx] = __float2half(fmaxf(acc, 0.f));
    }
}

// ---------------- reduce split-K + bias/relu/max/FC ------------
__global__ void maxfc_kernel(const float* __restrict__ b1b,
                             const float* __restrict__ fcw,
                             const float* __restrict__ fcb,
                             float* __restrict__ out) {
    int n = blockIdx.x;
    __shared__ float z[256];
    int c = threadIdx.x;
    float v = -3.4e38f;
    #pragma unroll
    for (int dd = 0; dd < 3; dd++) {
        float s = 0.f;
        #pragma unroll
        for (int zz = 0; zz < SPLIT2; zz++)
            s += g_C2p[(size_t)zz*M2*N2 + (size_t)(n*3 + dd)*N2 + c];
        v = fmaxf(v, s);
    }
    z[c] = fmaxf(v + b1b[c], 0.f);
    __syncthreads();
    int warp = threadIdx.x >> 5, lane = threadIdx.x & 31;
    for (int j = warp; j < NB; j += 8) {
        float s = 0.f;
        #pragma unroll
        for (int q = 0; q < 8; q++)
            s += z[lane + q*32] * fcw[j*256 + lane + q*32];
        #pragma unroll
        for (int off = 16; off; off >>= 1)
            s += __shfl_xor_sync(0xffffffffu, s, off);
        if (lane == 0) out[n*NB + j] = s + fcb[j];
    }
}

// ---------------- launch ----------------
extern "C" void kernel_launch(void* const* d_in, const int* in_sizes, int n_in,
                              void* d_out, int out_size) {
    const float* fmaps = (const float*)d_in[0];
    const float* boxes = (const float*)d_in[1];
    const int*   pids  = (const int*)d_in[2];
    const float* w1a   = (const float*)d_in[3];
    const float* b1a   = (const float*)d_in[4];
    const float* w1b   = (const float*)d_in[5];
    const float* b1b   = (const float*)d_in[6];
    const float* fcw   = (const float*)d_in[7];
    const float* fcb   = (const float*)d_in[8];
    float* out = (float*)d_out;

    __half *pR, *pB1, *pYh, *pB2, *pP;
    float *pC2p;
    cudaGetSymbolAddress((void**)&pR,  g_roiR);
    cudaGetSymbolAddress((void**)&pB1, g_B1);
    cudaGetSymbolAddress((void**)&pYh, g_yh);
    cudaGetSymbolAddress((void**)&pB2, g_B2);
    cudaGetSymbolAddress((void**)&pP,  g_P);
    cudaGetSymbolAddress((void**)&pC2p, g_C2p);

    cudaFuncSetAttribute(gemm_g1tap, cudaFuncAttributeMaxDynamicSharedMemorySize, 73728);
    cudaFuncSetAttribute(gemm_mma,   cudaFuncAttributeMaxDynamicSharedMemorySize, 49152);
    cudaFuncSetAttribute(prep_all,   cudaFuncAttributeMaxDynamicSharedMemorySize, 55296);

    // fused prep: roi->roiR | w1a | w1b | map — all independent
    prep_all<<<961, 256, 55296>>>(fmaps, boxes, pids, w1a, w1b);

    // G1 tap-sparse BK=64: P[z][1728x1536] += roiR x B1 over valid taps
    gemm_g1tap<<<dim3(N1/128, 27, SPLIT1), 256, 73728>>>(pR, pB1, pP);

    combine_kernel<<<NBOX*5, 256>>>(b1a);

    // G2 split-K=16: C2p[z][576x256] = y * B2^T, row remap (r/3)*5 + r%3
    gemm_mma<<<dim3(N2/128, M2/64, SPLIT2), 256, 49152>>>(
        pYh, pB2, KIT2, 4608, K2, 3, 5, pC2p, N2, (size_t)M2*N2);

    maxfc_kernel<<<NBOX, 256>>>(b1b, fcw, fcb, out);
}